// round 14
// baseline (speedup 1.0000x reference)
#include <cuda_runtime.h>
#include <cuda_bf16.h>
#include <cstdint>

#define NBL 4096          // B*L
#define DK  256           // MMA-covered K extent (index 256 handled exactly in fp32)
#define OD  64

// ---------------- device scratch (no allocs allowed) ----------------
__device__ __align__(16) __nv_bfloat16 g_x1h[NBL*DK], g_x1l[NBL*DK];
__device__ __align__(16) __nv_bfloat16 g_x2h[NBL*DK];
__device__ __align__(16) uint8_t g_x2h8[NBL*DK], g_x2l8[NBL*DK];           // fp8(x2), fp8(lo*256)
__device__ __align__(16) __nv_bfloat16 g_Uh[(size_t)OD*DK*DK], g_Ul[(size_t)OD*DK*DK];
__device__ __align__(16) __nv_bfloat16 g_Th[(size_t)NBL*OD*DK];
__device__ __align__(16) uint8_t g_Th8[(size_t)NBL*OD*DK], g_Tl8[(size_t)NBL*OD*DK];
__device__ float g_t256[NBL*OD];

// ---------------- helpers (baseline sm_90 ISA only: no tcgen05) ----------------
__device__ __forceinline__ uint32_t s2u(const void* p) {
    uint32_t a;
    asm("{ .reg .u64 t; cvta.to.shared.u64 t, %1; cvt.u32.u64 %0, t; }" : "=r"(a) : "l"(p));
    return a;
}
__device__ __forceinline__ void cp16(uint32_t s, const void* g) {
    asm volatile("cp.async.cg.shared.global [%0], [%1], 16;" :: "r"(s), "l"(g));
}
__device__ __forceinline__ void cp_commit() {
    asm volatile("cp.async.commit_group;");
}
template<int N> __device__ __forceinline__ void cp_wait() {
    asm volatile("cp.async.wait_group %0;" :: "n"(N));
}
__device__ __forceinline__ void ldsm4(uint32_t r[4], uint32_t addr) {
    asm volatile("ldmatrix.sync.aligned.m8n8.x4.shared.b16 {%0,%1,%2,%3}, [%4];"
        : "=r"(r[0]), "=r"(r[1]), "=r"(r[2]), "=r"(r[3]) : "r"(addr));
}
__device__ __forceinline__ void mma16(float c[4], const uint32_t a[4], uint32_t b0, uint32_t b1) {
    asm volatile("mma.sync.aligned.m16n8k16.row.col.f32.bf16.bf16.f32 "
        "{%0,%1,%2,%3}, {%4,%5,%6,%7}, {%8,%9}, {%0,%1,%2,%3};"
        : "+f"(c[0]), "+f"(c[1]), "+f"(c[2]), "+f"(c[3])
        : "r"(a[0]), "r"(a[1]), "r"(a[2]), "r"(a[3]), "r"(b0), "r"(b1));
}
__device__ __forceinline__ void mma8(float c[4], const uint32_t a[4], uint32_t b0, uint32_t b1) {
    asm volatile("mma.sync.aligned.m16n8k32.row.col.f32.e4m3.e4m3.f32 "
        "{%0,%1,%2,%3}, {%4,%5,%6,%7}, {%8,%9}, {%0,%1,%2,%3};"
        : "+f"(c[0]), "+f"(c[1]), "+f"(c[2]), "+f"(c[3])
        : "r"(a[0]), "r"(a[1]), "r"(a[2]), "r"(a[3]), "r"(b0), "r"(b1));
}
// pack two floats to e4m3x2; low byte = lo operand
__device__ __forceinline__ uint16_t f2e4m3x2(float hi, float lo) {
    uint16_t d;
    asm("cvt.rn.satfinite.e4m3x2.f32 %0, %1, %2;" : "=h"(d) : "f"(hi), "f"(lo));
    return d;
}

// ================= K1: per-chunk A+B buffers, 2-stage, 3 CTAs/SM (R10 shape) =====
#define AHOFF 0
#define ALOFF 10240u   // 128 rows * 80B
#define BHOFF 20480u
#define BLOFF 25600u   // + 64 rows * 80B
#define BUFSZ 30720u
#define SMEMB (256u + 2u*BUFSZ)   // 61,696 B -> 3 CTAs/SM

__device__ __forceinline__ void copy_chunk(uint32_t bufb,
        const __nv_bfloat16* Ah, const __nv_bfloat16* Al,
        const __nv_bfloat16* Bh, const __nv_bfloat16* Bl, int k0) {
    const int tid = threadIdx.x;
    #pragma unroll
    for (int u = tid; u < 512; u += 256) {            // A: 128 rows x 4 16B-units
        int row = u >> 2, c = u & 3;
        uint32_t d = bufb + row * 80 + c * 16;
        const size_t go = (size_t)row * DK + k0 + c * 8;
        cp16(d + AHOFF, Ah + go);
        cp16(d + ALOFF, Al + go);
    }
    {                                                  // B: 64 rows x 4 units = 256
        int row = tid >> 2, c = tid & 3;
        uint32_t d = bufb + row * 80 + c * 16;
        const size_t go = (size_t)row * DK + k0 + c * 8;
        cp16(d + BHOFF, Bh + go);
        cp16(d + BLOFF, Bl + go);
    }
    cp_commit();
}

__device__ __forceinline__ void compute_chunk(uint32_t bufb, int lane, int wm, int wn,
                                              float c[2][4][4]) {
    uint32_t rowA = bufb + AHOFF + (uint32_t)((wm * 32 + (lane & 15)) * 80 + ((lane >> 4) * 16));
    uint32_t rowB = bufb + BHOFF + (uint32_t)((wn * 32 + (lane & 15)) * 80 + ((lane >> 4) * 16));
    #pragma unroll
    for (int ks = 0; ks < 2; ks++) {
        uint32_t aH[2][4], aL[2][4], bH[2][4], bL[2][4];
        #pragma unroll
        for (int t = 0; t < 2; t++) {
            ldsm4(aH[t], rowA + t * 1280 + ks * 32);
            ldsm4(aL[t], rowA + (ALOFF - AHOFF) + t * 1280 + ks * 32);
        }
        #pragma unroll
        for (int g = 0; g < 2; g++) {
            ldsm4(bH[g], rowB + g * 1280 + ks * 32);
            ldsm4(bL[g], rowB + (BLOFF - BHOFF) + g * 1280 + ks * 32);
        }
        #pragma unroll
        for (int t = 0; t < 2; t++)
            #pragma unroll
            for (int g = 0; g < 2; g++)
                #pragma unroll
                for (int h = 0; h < 2; h++) {
                    float* acc = c[t][g * 2 + h];
                    mma16(acc, aH[t], bH[g][h], bH[g][h + 2]);   // hi*hi
                    mma16(acc, aH[t], bL[g][h], bL[g][h + 2]);   // hi*lo
                    mma16(acc, aL[t], bH[g][h], bH[g][h + 2]);   // lo*hi
                }
    }
}

__global__ __launch_bounds__(256, 3) void k1_mm(const float* __restrict__ U) {
    extern __shared__ char sm[];
    uint32_t sb = s2u(sm);
    const int tid = threadIdx.x, lane = tid & 31, wid = tid >> 5;
    const int wm = wid >> 1, wn = wid & 1;
    const int bl0 = blockIdx.x * 128, o = blockIdx.y, i0 = blockIdx.z * 64;

    float* ub = (float*)sm;   // bias col U[o, i0+n, 256]
    if (tid < 64) ub[tid] = U[((size_t)o * 257 + i0 + tid) * 257 + 256];

    float c[2][4][4];
    #pragma unroll
    for (int t = 0; t < 2; t++)
        #pragma unroll
        for (int q = 0; q < 4; q++)
            #pragma unroll
            for (int e = 0; e < 4; e++) c[t][q][e] = 0.f;

    const __nv_bfloat16* Ah = g_x1h + (size_t)bl0 * DK;
    const __nv_bfloat16* Al = g_x1l + (size_t)bl0 * DK;
    const __nv_bfloat16* Bh = g_Uh + (size_t)o * DK * DK + (size_t)i0 * DK;
    const __nv_bfloat16* Bl = g_Ul + (size_t)o * DK * DK + (size_t)i0 * DK;

    const uint32_t b0 = sb + 256, b1 = b0 + BUFSZ;
    copy_chunk(b0, Ah, Al, Bh, Bl, 0);
    #pragma unroll 1
    for (int kc = 0; kc < 8; kc++) {
        if (kc < 7) {
            copy_chunk(((kc + 1) & 1) ? b1 : b0, Ah, Al, Bh, Bl, (kc + 1) * 32);
            cp_wait<1>();
        } else {
            cp_wait<0>();
        }
        __syncthreads();
        compute_chunk((kc & 1) ? b1 : b0, lane, wm, wn, c);
        __syncthreads();
    }

    // epilogue: T hi (bf16) + T hi/lo in fp8 (lo scaled x256)
    const int mr = wm * 32 + (lane >> 2);
    const int nc = wn * 32 + (lane & 3) * 2;
    #pragma unroll
    for (int t = 0; t < 2; t++)
        #pragma unroll
        for (int n8 = 0; n8 < 4; n8++) {
            int n = nc + n8 * 8;
            float b0f = ub[n], b1f = ub[n + 1];
            #pragma unroll
            for (int h = 0; h < 2; h++) {
                int m = bl0 + mr + t * 16 + h * 8;
                float v0 = c[t][n8][h * 2 + 0] + b0f;
                float v1 = c[t][n8][h * 2 + 1] + b1f;
                __nv_bfloat16 h0 = __float2bfloat16(v0);
                __nv_bfloat16 h1 = __float2bfloat16(v1);
                float l0 = v0 - __bfloat162float(h0);
                float l1 = v1 - __bfloat162float(h1);
                __nv_bfloat162 ph; ph.x = h0; ph.y = h1;
                size_t base = ((size_t)m * OD + o) * DK + i0 + n;
                *reinterpret_cast<__nv_bfloat162*>(g_Th + base) = ph;
                *reinterpret_cast<uint16_t*>(g_Th8 + base) = f2e4m3x2(v1, v0);
                *reinterpret_cast<uint16_t*>(g_Tl8 + base) = f2e4m3x2(l1 * 256.f, l0 * 256.f);
            }
        }
}

// ---------------- preprocessing ----------------
// fused x1+x2 split; x2 also emits fp8 hi and fp8(lo*256)
__global__ __launch_bounds__(256) void xsplit(const float* __restrict__ s1,
                                              const float* __restrict__ s2) {
    int i = (blockIdx.x & 4095) * 256 + threadIdx.x;
    if (blockIdx.x < 4096) {
        float x = s1[i];
        __nv_bfloat16 h = __float2bfloat16(x);
        g_x1h[i] = h; g_x1l[i] = __float2bfloat16(x - __bfloat162float(h));
    } else {
        float x = s2[i];
        __nv_bfloat16 h = __float2bfloat16(x);
        float l = x - __bfloat162float(h);
        g_x2h[i] = h;
        g_x2h8[i] = (uint8_t)(f2e4m3x2(0.f, x) & 0xFF);
        g_x2l8[i] = (uint8_t)(f2e4m3x2(0.f, l * 256.f) & 0xFF);
    }
}
__global__ __launch_bounds__(256) void usplit(const float* __restrict__ U) {
    size_t idx = (size_t)blockIdx.x * 256 + threadIdx.x;   // 64*256*256
    int o = (int)(idx >> 16), r = (int)(idx & 65535), i = r >> 8, j = r & 255;
    float x = U[((size_t)o * 257 + i) * 257 + j];
    __nv_bfloat16 h = __float2bfloat16(x);
    g_Uh[idx] = h; g_Ul[idx] = __float2bfloat16(x - __bfloat162float(h));
}

// t256[bl,o] = sum_j U[o,256,j]*x1a[bl,j] + U[o,256,256]  (exact fp32)
__global__ __launch_bounds__(256) void t256_k(const float* __restrict__ x1,
                                              const float* __restrict__ U) {
    extern __shared__ char sm[];
    float* Us  = (float*)sm;              // 64 x 261 (261%32=5 -> conflict-free)
    float* x1s = (float*)sm + 64 * 261;   // 16 x 256
    const int bl0 = blockIdx.x * 16, tid = threadIdx.x;

    for (int e = tid; e < 64 * 257; e += 256) {
        int o = e / 257, j = e - o * 257;
        Us[o * 261 + j] = U[((size_t)o * 257 + 256) * 257 + j];
    }
    for (int e = tid; e < 16 * 256; e += 256)
        x1s[e] = x1[(size_t)(bl0 + (e >> 8)) * 256 + (e & 255)];
    __syncthreads();

    const int blq = tid >> 6, o = tid & 63;
    const float* ur = Us + o * 261;
    float acc[4];
    #pragma unroll
    for (int v = 0; v < 4; v++) acc[v] = ur[256];
    #pragma unroll 4
    for (int j = 0; j < 256; j++) {
        float u = ur[j];
        #pragma unroll
        for (int v = 0; v < 4; v++)
            acc[v] = fmaf(x1s[(blq * 4 + v) * 256 + j], u, acc[v]);
    }
    #pragma unroll
    for (int v = 0; v < 4; v++)
        g_t256[(size_t)(bl0 + blq * 4 + v) * 64 + o] = acc[v];
}

// ========== K2: persistent-B (bf16 hi + fp8 hi/lo), fp8 cross-term MMAs ==========
// smem: t2 256 | BH(bf16) 64x528 | BH8 64x272 | BL8 64x272 | A stages x2
//   A stage: aH(bf16,80B rows) 10240 | aH8(48B rows) 6144 | aL8 6144 = 22528
#define K2_BH   256u
#define K2_BH8  34048u     // 256 + 33792
#define K2_BL8  51456u     // + 17408
#define K2_A0   68864u     // + 17408
#define K2_ASZ  22528u
#define K2_A1   91392u
#define K2_SMEM 113920u    // 2 CTAs/SM

__device__ __forceinline__ void copy_B_full(uint32_t sb,
        const __nv_bfloat16* Bh, const uint8_t* B8h, const uint8_t* B8l) {
    const int tid = threadIdx.x;
    #pragma unroll
    for (int u = tid; u < 2048; u += 256) {   // bf16 hi: 64 rows x 32 16B-units
        int row = u >> 5, c = u & 31;
        cp16(sb + K2_BH + row * 528 + c * 16, Bh + (size_t)row * DK + c * 8);
    }
    #pragma unroll
    for (int u = tid; u < 1024; u += 256) {   // fp8: 64 rows x 16 16B-units each
        int row = u >> 4, c = u & 15;
        cp16(sb + K2_BH8 + row * 272 + c * 16, B8h + (size_t)row * DK + c * 16);
        cp16(sb + K2_BL8 + row * 272 + c * 16, B8l + (size_t)row * DK + c * 16);
    }
}
__device__ __forceinline__ void copy_A_chunk(uint32_t bufb,
        const __nv_bfloat16* Ah, const uint8_t* Ah8, const uint8_t* Al8, int nx) {
    const int tid = threadIdx.x;
    const int mb2 = nx >> 3, k0 = (nx & 7) * 32;     // k0: elements == bytes (fp8)
    #pragma unroll
    for (int u = tid; u < 512; u += 256) {    // aH bf16: 128 rows x 4 units
        int row = u >> 2, c = u & 3;
        cp16(bufb + row * 80 + c * 16,
             Ah + (size_t)(mb2 * 128 + row) * DK + k0 + c * 8);
    }
    {                                          // fp8: 128 rows x 2 units each
        int row = tid >> 1, c = tid & 1;
        size_t go = (size_t)(mb2 * 128 + row) * DK + k0 + c * 16;
        cp16(bufb + 10240u + row * 48 + c * 16, Ah8 + go);
        cp16(bufb + 16384u + row * 48 + c * 16, Al8 + go);
    }
    cp_commit();
}

__device__ __forceinline__ void compute_chunk_k2(uint32_t ab, uint32_t sb, int kc,
        int lane, int wm, int wn, float c[2][4][4], float c2[2][4][4]) {
    const uint32_t u16o = (uint32_t)((lane >> 4) * 16);
    const uint32_t rowA  = ab + (uint32_t)((wm * 32 + (lane & 15)) * 80) + u16o;
    const uint32_t rowB  = sb + K2_BH + (uint32_t)((wn * 32 + (lane & 15)) * 528) + u16o
                         + (uint32_t)(kc * 64);
    // bf16 hi*hi
    #pragma unroll
    for (int ks = 0; ks < 2; ks++) {
        uint32_t aH[2][4], bH[2][4];
        #pragma unroll
        for (int t = 0; t < 2; t++) ldsm4(aH[t], rowA + t * 1280 + ks * 32);
        #pragma unroll
        for (int g = 0; g < 2; g++) ldsm4(bH[g], rowB + g * 8448 + ks * 32);
        #pragma unroll
        for (int t = 0; t < 2; t++)
            #pragma unroll
            for (int g = 0; g < 2; g++)
                #pragma unroll
                for (int h = 0; h < 2; h++)
                    mma16(c[t][g * 2 + h], aH[t], bH[g][h], bH[g][h + 2]);
    }
    // fp8 cross terms (k32): aH8*bL8 + aL8*bH8, accumulated with x256 scale in c2
    const uint32_t rowA8 = ab + 10240u + (uint32_t)((wm * 32 + (lane & 15)) * 48) + u16o;
    const uint32_t rowB8 = sb + K2_BH8 + (uint32_t)((wn * 32 + (lane & 15)) * 272) + u16o
                         + (uint32_t)(kc * 32);
    uint32_t a8H[2][4], a8L[2][4], b8H[2][4], b8L[2][4];
    #pragma unroll
    for (int t = 0; t < 2; t++) {
        ldsm4(a8H[t], rowA8 + t * 768);
        ldsm4(a8L[t], rowA8 + 6144u + t * 768);
    }
    #pragma unroll
    for (int q = 0; q < 2; q++) {
        ldsm4(b8H[q], rowB8 + q * 4352);
        ldsm4(b8L[q], rowB8 + (K2_BL8 - K2_BH8) + q * 4352);
    }
    #pragma unroll
    for (int t = 0; t < 2; t++)
        #pragma unroll
        for (int q = 0; q < 2; q++)
            #pragma unroll
            for (int j = 0; j < 2; j++) {
                float* acc = c2[t][q * 2 + j];
                mma8(acc, a8H[t], b8L[q][j], b8L[q][j + 2]);
                mma8(acc, a8L[t], b8H[q][j], b8H[q][j + 2]);
            }
}

__global__ __launch_bounds__(256, 2) void k2_mm(float* __restrict__ out) {
    extern __shared__ char sm[];
    uint32_t sb = s2u(sm);
    const int tid = threadIdx.x, lane = tid & 31, wid = tid >> 5;
    const int wm = wid >> 1, wn = wid & 1;
    const int bl = blockIdx.x, b = bl >> 9;

    float* t2 = (float*)sm;   // T[bl,o,256] broadcast (x2a[m,256]==1)
    if (tid < 64) t2[tid] = g_t256[(size_t)bl * OD + tid];

    const __nv_bfloat16* Ahb = g_x2h + (size_t)(b * 512) * DK;
    const uint8_t* Ah8b = g_x2h8 + (size_t)(b * 512) * DK;
    const uint8_t* Al8b = g_x2l8 + (size_t)(b * 512) * DK;

    copy_B_full(sb, g_Th + (size_t)bl * OD * DK,
                g_Th8 + (size_t)bl * OD * DK, g_Tl8 + (size_t)bl * OD * DK);
    cp_commit();
    copy_A_chunk(sb + K2_A0, Ahb, Ah8b, Al8b, 0);

    const uint32_t abuf[2] = { sb + K2_A0, sb + K2_A1 };
    const int mr = wm * 32 + (lane >> 2);
    const int nc = wn * 32 + (lane & 3) * 2;

    #pragma unroll 1
    for (int mb = 0; mb < 4; mb++) {
        float c[2][4][4], c2[2][4][4];
        #pragma unroll
        for (int t = 0; t < 2; t++)
            #pragma unroll
            for (int n = 0; n < 4; n++)
                #pragma unroll
                for (int e = 0; e < 4; e++) { c[t][n][e] = 0.f; c2[t][n][e] = 0.f; }

        #pragma unroll 1
        for (int kc = 0; kc < 8; kc++) {
            int it = mb * 8 + kc;
            if (it < 31) {
                copy_A_chunk(abuf[(it + 1) & 1], Ahb, Ah8b, Al8b, it + 1);
                cp_wait<1>();
            } else {
                cp_wait<0>();
            }
            __syncthreads();
            compute_chunk_k2(abuf[it & 1], sb, kc, lane, wm, wn, c, c2);
            __syncthreads();
        }

        #pragma unroll
        for (int t = 0; t < 2; t++)
            #pragma unroll
            for (int n8 = 0; n8 < 4; n8++) {
                int n = nc + n8 * 8;
                float b0f = t2[n], b1f = t2[n + 1];
                #pragma unroll
                for (int h = 0; h < 2; h++) {
                    int m = mb * 128 + mr + t * 16 + h * 8;
                    float2 v;
                    v.x = c[t][n8][h * 2 + 0] + c2[t][n8][h * 2 + 0] * (1.f / 256.f) + b0f;
                    v.y = c[t][n8][h * 2 + 1] + c2[t][n8][h * 2 + 1] * (1.f / 256.f) + b1f;
                    *reinterpret_cast<float2*>(out + ((size_t)bl * 512 + m) * OD + n) = v;
                }
            }
    }
}

// ---------------- launch ----------------
extern "C" void kernel_launch(void* const* d_in, const int* in_sizes, int n_in,
                              void* d_out, int out_size) {
    const float* x1 = (const float*)d_in[0];   // (8,512,1,256)
    const float* x2 = (const float*)d_in[1];   // (8,1,512,256)
    const float* U  = (const float*)d_in[2];   // (64,257,257)
    float* out = (float*)d_out;                // (8,512,512,64)

    cudaFuncSetAttribute(t256_k, cudaFuncAttributeMaxDynamicSharedMemorySize, 83200);
    cudaFuncSetAttribute(k1_mm, cudaFuncAttributeMaxDynamicSharedMemorySize, (int)SMEMB);
    cudaFuncSetAttribute(k2_mm, cudaFuncAttributeMaxDynamicSharedMemorySize, (int)K2_SMEM);

    xsplit<<<8192, 256>>>(x1, x2);
    usplit<<<16384, 256>>>(U);
    t256_k<<<256, 256, 83200>>>(x1, U);
    k1_mm<<<dim3(32, 64, 4), 256, SMEMB>>>(U);
    k2_mm<<<4096, 256, K2_SMEM>>>(out);
}

// round 15
// speedup vs baseline: 1.1870x; 1.1870x over previous
#include <cuda_runtime.h>
#include <cuda_bf16.h>
#include <cstdint>

#define NBL 4096          // B*L
#define DK  256           // MMA-covered K extent (index 256 handled exactly in fp32)
#define OD  64

// ---------------- device scratch (no allocs allowed) ----------------
__device__ __align__(16) __nv_bfloat16 g_x1h[NBL*DK], g_x1l[NBL*DK];
__device__ __align__(16) __nv_bfloat16 g_x2h[NBL*DK], g_x2l[NBL*DK];
__device__ __align__(16) __nv_bfloat16 g_Uh[(size_t)OD*DK*DK], g_Ul[(size_t)OD*DK*DK];
__device__ __align__(16) __nv_bfloat16 g_Th[(size_t)NBL*OD*DK], g_Tl[(size_t)NBL*OD*DK];
__device__ float g_t256[NBL*OD];

// ---------------- helpers (baseline sm_90 ISA only: no tcgen05) ----------------
__device__ __forceinline__ uint32_t s2u(const void* p) {
    uint32_t a;
    asm("{ .reg .u64 t; cvta.to.shared.u64 t, %1; cvt.u32.u64 %0, t; }" : "=r"(a) : "l"(p));
    return a;
}
__device__ __forceinline__ void cp16(uint32_t s, const void* g) {
    asm volatile("cp.async.cg.shared.global [%0], [%1], 16;" :: "r"(s), "l"(g));
}
__device__ __forceinline__ void cp_commit() {
    asm volatile("cp.async.commit_group;");
}
template<int N> __device__ __forceinline__ void cp_wait() {
    asm volatile("cp.async.wait_group %0;" :: "n"(N));
}
__device__ __forceinline__ void ldsm4(uint32_t r[4], uint32_t addr) {
    asm volatile("ldmatrix.sync.aligned.m8n8.x4.shared.b16 {%0,%1,%2,%3}, [%4];"
        : "=r"(r[0]), "=r"(r[1]), "=r"(r[2]), "=r"(r[3]) : "r"(addr));
}
__device__ __forceinline__ void mma16(float c[4], const uint32_t a[4], uint32_t b0, uint32_t b1) {
    asm volatile("mma.sync.aligned.m16n8k16.row.col.f32.bf16.bf16.f32 "
        "{%0,%1,%2,%3}, {%4,%5,%6,%7}, {%8,%9}, {%0,%1,%2,%3};"
        : "+f"(c[0]), "+f"(c[1]), "+f"(c[2]), "+f"(c[3])
        : "r"(a[0]), "r"(a[1]), "r"(a[2]), "r"(a[3]), "r"(b0), "r"(b1));
}

// ================= K1: per-chunk A+B buffers, 2-stage, 3 CTAs/SM =================
// rows padded to 80B (k=32 bf16 = 64B + 16B pad) -> conflict-free ldmatrix
#define AHOFF 0
#define ALOFF 10240u   // 128 rows * 80B
#define BHOFF 20480u
#define BLOFF 25600u   // + 64 rows * 80B
#define BUFSZ 30720u
#define SMEMB (256u + 2u*BUFSZ)   // 61,696 B -> 3 CTAs/SM

__device__ __forceinline__ void copy_chunk(uint32_t bufb,
        const __nv_bfloat16* Ah, const __nv_bfloat16* Al,
        const __nv_bfloat16* Bh, const __nv_bfloat16* Bl, int k0) {
    const int tid = threadIdx.x;
    #pragma unroll
    for (int u = tid; u < 512; u += 256) {            // A: 128 rows x 4 16B-units
        int row = u >> 2, c = u & 3;
        uint32_t d = bufb + row * 80 + c * 16;
        const size_t go = (size_t)row * DK + k0 + c * 8;
        cp16(d + AHOFF, Ah + go);
        cp16(d + ALOFF, Al + go);
    }
    {                                                  // B: 64 rows x 4 units = 256
        int row = tid >> 2, c = tid & 3;
        uint32_t d = bufb + row * 80 + c * 16;
        const size_t go = (size_t)row * DK + k0 + c * 8;
        cp16(d + BHOFF, Bh + go);
        cp16(d + BLOFF, Bl + go);
    }
    cp_commit();
}

__device__ __forceinline__ void compute_chunk(uint32_t bufb, int lane, int wm, int wn,
                                              float c[2][4][4]) {
    uint32_t rowA = bufb + AHOFF + (uint32_t)((wm * 32 + (lane & 15)) * 80 + ((lane >> 4) * 16));
    uint32_t rowB = bufb + BHOFF + (uint32_t)((wn * 32 + (lane & 15)) * 80 + ((lane >> 4) * 16));
    #pragma unroll
    for (int ks = 0; ks < 2; ks++) {
        uint32_t aH[2][4], aL[2][4], bH[2][4], bL[2][4];
        #pragma unroll
        for (int t = 0; t < 2; t++) {
            ldsm4(aH[t], rowA + t * 1280 + ks * 32);
            ldsm4(aL[t], rowA + (ALOFF - AHOFF) + t * 1280 + ks * 32);
        }
        #pragma unroll
        for (int g = 0; g < 2; g++) {
            ldsm4(bH[g], rowB + g * 1280 + ks * 32);
            ldsm4(bL[g], rowB + (BLOFF - BHOFF) + g * 1280 + ks * 32);
        }
        #pragma unroll
        for (int t = 0; t < 2; t++)
            #pragma unroll
            for (int g = 0; g < 2; g++)
                #pragma unroll
                for (int h = 0; h < 2; h++) {
                    float* acc = c[t][g * 2 + h];
                    mma16(acc, aH[t], bH[g][h], bH[g][h + 2]);   // hi*hi
                    mma16(acc, aH[t], bL[g][h], bL[g][h + 2]);   // hi*lo
                    mma16(acc, aL[t], bH[g][h], bH[g][h + 2]);   // lo*hi
                }
    }
}

__device__ __forceinline__ void run_gemm(uint32_t sb,
        const __nv_bfloat16* Ah, const __nv_bfloat16* Al,
        const __nv_bfloat16* Bh, const __nv_bfloat16* Bl,
        int lane, int wm, int wn, float c[2][4][4]) {
    #pragma unroll
    for (int t = 0; t < 2; t++)
        #pragma unroll
        for (int n = 0; n < 4; n++)
            #pragma unroll
            for (int e = 0; e < 4; e++) c[t][n][e] = 0.f;

    const uint32_t b0 = sb + 256, b1 = b0 + BUFSZ;
    copy_chunk(b0, Ah, Al, Bh, Bl, 0);
    #pragma unroll 1
    for (int kc = 0; kc < 8; kc++) {
        if (kc < 7) {
            copy_chunk(((kc + 1) & 1) ? b1 : b0, Ah, Al, Bh, Bl, (kc + 1) * 32);
            cp_wait<1>();
        } else {
            cp_wait<0>();
        }
        __syncthreads();
        compute_chunk((kc & 1) ? b1 : b0, lane, wm, wn, c);
        __syncthreads();
    }
}

// ---------------- preprocessing ----------------
// fused x1+x2 split: grid 8192, first half x1, second half x2
__global__ __launch_bounds__(256) void xsplit(const float* __restrict__ s1,
                                              const float* __restrict__ s2) {
    int i = (blockIdx.x & 4095) * 256 + threadIdx.x;
    if (blockIdx.x < 4096) {
        float x = s1[i];
        __nv_bfloat16 h = __float2bfloat16(x);
        g_x1h[i] = h; g_x1l[i] = __float2bfloat16(x - __bfloat162float(h));
    } else {
        float x = s2[i];
        __nv_bfloat16 h = __float2bfloat16(x);
        g_x2h[i] = h; g_x2l[i] = __float2bfloat16(x - __bfloat162float(h));
    }
}
// 4 elements/thread; scalar loads (257-stride rows break vector alignment),
// packed 8B stores per split tensor.
__global__ __launch_bounds__(256) void usplit(const float* __restrict__ U) {
    size_t idx = ((size_t)blockIdx.x * 256 + threadIdx.x) * 4;   // 64*256*256 total
    int o = (int)(idx >> 16), r = (int)(idx & 65535), i = r >> 8, j = r & 255;
    const float* src = U + ((size_t)o * 257 + i) * 257 + j;
    union { __nv_bfloat16 b[4]; uint2 v; } ph, pl;
    #pragma unroll
    for (int e = 0; e < 4; e++) {
        float x = src[e];
        __nv_bfloat16 h = __float2bfloat16(x);
        ph.b[e] = h;
        pl.b[e] = __float2bfloat16(x - __bfloat162float(h));
    }
    *reinterpret_cast<uint2*>(g_Uh + idx) = ph.v;
    *reinterpret_cast<uint2*>(g_Ul + idx) = pl.v;
}

// t256[bl,o] = sum_j U[o,256,j]*x1a[bl,j] + U[o,256,256]  (exact fp32)
__global__ __launch_bounds__(256) void t256_k(const float* __restrict__ x1,
                                              const float* __restrict__ U) {
    extern __shared__ char sm[];
    float* Us  = (float*)sm;              // 64 x 261 (261%32=5 -> conflict-free)
    float* x1s = (float*)sm + 64 * 261;   // 16 x 256
    const int bl0 = blockIdx.x * 16, tid = threadIdx.x;

    for (int e = tid; e < 64 * 257; e += 256) {
        int o = e / 257, j = e - o * 257;
        Us[o * 261 + j] = U[((size_t)o * 257 + 256) * 257 + j];
    }
    for (int e = tid; e < 16 * 256; e += 256)
        x1s[e] = x1[(size_t)(bl0 + (e >> 8)) * 256 + (e & 255)];
    __syncthreads();

    const int blq = tid >> 6, o = tid & 63;
    const float* ur = Us + o * 261;
    float acc[4];
    #pragma unroll
    for (int v = 0; v < 4; v++) acc[v] = ur[256];
    #pragma unroll 4
    for (int j = 0; j < 256; j++) {
        float u = ur[j];
        #pragma unroll
        for (int v = 0; v < 4; v++)
            acc[v] = fmaf(x1s[(blq * 4 + v) * 256 + j], u, acc[v]);
    }
    #pragma unroll
    for (int v = 0; v < 4; v++)
        g_t256[(size_t)(bl0 + blq * 4 + v) * 64 + o] = acc[v];
}

// ---------------- K1: T[bl,o,i] = sum_j U[o,i,j]*x1a[bl,j] ----------------
__global__ __launch_bounds__(256, 3) void k1_mm(const float* __restrict__ U) {
    extern __shared__ char sm[];
    uint32_t sb = s2u(sm);
    const int tid = threadIdx.x, lane = tid & 31, wid = tid >> 5;
    const int wm = wid >> 1, wn = wid & 1;
    const int bl0 = blockIdx.x * 128, o = blockIdx.y, i0 = blockIdx.z * 64;

    float* ub = (float*)sm;   // bias col U[o, i0+n, 256]
    if (tid < 64) ub[tid] = U[((size_t)o * 257 + i0 + tid) * 257 + 256];

    float c[2][4][4];
    run_gemm(sb,
             g_x1h + (size_t)bl0 * DK, g_x1l + (size_t)bl0 * DK,
             g_Uh + (size_t)o * DK * DK + (size_t)i0 * DK,
             g_Ul + (size_t)o * DK * DK + (size_t)i0 * DK,
             lane, wm, wn, c);

    const int mr = wm * 32 + (lane >> 2);
    const int nc = wn * 32 + (lane & 3) * 2;
    #pragma unroll
    for (int t = 0; t < 2; t++)
        #pragma unroll
        for (int n8 = 0; n8 < 4; n8++) {
            int n = nc + n8 * 8;
            float b0f = ub[n], b1f = ub[n + 1];
            #pragma unroll
            for (int h = 0; h < 2; h++) {
                int m = bl0 + mr + t * 16 + h * 8;
                float v0 = c[t][n8][h * 2 + 0] + b0f;
                float v1 = c[t][n8][h * 2 + 1] + b1f;
                __nv_bfloat16 h0 = __float2bfloat16(v0);
                __nv_bfloat16 h1 = __float2bfloat16(v1);
                __nv_bfloat162 ph; ph.x = h0; ph.y = h1;
                __nv_bfloat162 pl;
                pl.x = __float2bfloat16(v0 - __bfloat162float(h0));
                pl.y = __float2bfloat16(v1 - __bfloat162float(h1));
                size_t base = ((size_t)m * OD + o) * DK + i0 + n;
                *reinterpret_cast<__nv_bfloat162*>(g_Th + base) = ph;
                *reinterpret_cast<__nv_bfloat162*>(g_Tl + base) = pl;
            }
        }
}

// ================= K2: persistent-B, one CTA per bl, internal m-loop =================
// smem: [0,256) t2 | BH 64x528B | BL | A double buffers (80B rows)
#define K2_BH   256u
#define K2_BL   34048u     // 256 + 64*528
#define K2_A0   67840u     // 256 + 2*33792
#define K2_A1   88320u     // + 20480
#define K2_SMEM 108800u    // -> 2 CTAs/SM

__device__ __forceinline__ void copy_B_full(uint32_t bbase,
        const __nv_bfloat16* Bh, const __nv_bfloat16* Bl) {
    const int tid = threadIdx.x;
    #pragma unroll
    for (int u = tid; u < 2048; u += 256) {   // 64 rows x 32 16B-units
        int row = u >> 5, c = u & 31;
        uint32_t d = bbase + row * 528 + c * 16;
        size_t go = (size_t)row * DK + c * 8;
        cp16(d, Bh + go);
        cp16(d + 33792u, Bl + go);
    }
}
__device__ __forceinline__ void copy_A_chunk(uint32_t bufb,
        const __nv_bfloat16* Ah, const __nv_bfloat16* Al, int k0) {
    const int tid = threadIdx.x;
    #pragma unroll
    for (int u = tid; u < 512; u += 256) {    // 128 rows x 4 16B-units
        int row = u >> 2, c = u & 3;
        uint32_t d = bufb + row * 80 + c * 16;
        size_t go = (size_t)row * DK + k0 + c * 8;
        cp16(d, Ah + go);
        cp16(d + 10240u, Al + go);
    }
}
__device__ __forceinline__ void compute_chunk_k2(uint32_t ab, uint32_t bb, int koffB,
                                                 int lane, int wm, int wn, float c[2][4][4]) {
    uint32_t rowA = ab + (uint32_t)((wm * 32 + (lane & 15)) * 80 + ((lane >> 4) * 16));
    uint32_t rowB = bb + (uint32_t)((wn * 32 + (lane & 15)) * 528 + ((lane >> 4) * 16) + koffB);
    #pragma unroll
    for (int ks = 0; ks < 2; ks++) {
        uint32_t aH[2][4], aL[2][4], bH[2][4], bL[2][4];
        #pragma unroll
        for (int t = 0; t < 2; t++) {
            ldsm4(aH[t], rowA + t * 1280 + ks * 32);
            ldsm4(aL[t], rowA + 10240u + t * 1280 + ks * 32);
        }
        #pragma unroll
        for (int g = 0; g < 2; g++) {
            ldsm4(bH[g], rowB + g * 8448 + ks * 32);          // 16 rows * 528B
            ldsm4(bL[g], rowB + 33792u + g * 8448 + ks * 32);
        }
        #pragma unroll
        for (int t = 0; t < 2; t++)
            #pragma unroll
            for (int g = 0; g < 2; g++)
                #pragma unroll
                for (int h = 0; h < 2; h++) {
                    float* acc = c[t][g * 2 + h];
                    mma16(acc, aH[t], bH[g][h], bH[g][h + 2]);
                    mma16(acc, aH[t], bL[g][h], bL[g][h + 2]);
                    mma16(acc, aL[t], bH[g][h], bH[g][h + 2]);
                }
    }
}

__global__ __launch_bounds__(256, 2) void k2_mm(float* __restrict__ out) {
    extern __shared__ char sm[];
    uint32_t sb = s2u(sm);
    const int tid = threadIdx.x, lane = tid & 31, wid = tid >> 5;
    const int wm = wid >> 1, wn = wid & 1;
    const int bl = blockIdx.x, b = bl >> 9;

    float* t2 = (float*)sm;   // T[bl,o,256] broadcast (x2a[m,256]==1)
    if (tid < 64) t2[tid] = g_t256[(size_t)bl * OD + tid];

    const __nv_bfloat16* Ahb = g_x2h + (size_t)(b * 512) * DK;
    const __nv_bfloat16* Alb = g_x2l + (size_t)(b * 512) * DK;

    copy_B_full(sb + K2_BH, g_Th + (size_t)bl * OD * DK, g_Tl + (size_t)bl * OD * DK);
    cp_commit();
    copy_A_chunk(sb + K2_A0, Ahb, Alb, 0);
    cp_commit();

    const uint32_t abuf[2] = { sb + K2_A0, sb + K2_A1 };
    const int mr = wm * 32 + (lane >> 2);
    const int nc = wn * 32 + (lane & 3) * 2;

    #pragma unroll 1
    for (int mb = 0; mb < 4; mb++) {
        float c[2][4][4];
        #pragma unroll
        for (int t = 0; t < 2; t++)
            #pragma unroll
            for (int n = 0; n < 4; n++)
                #pragma unroll
                for (int e = 0; e < 4; e++) c[t][n][e] = 0.f;

        #pragma unroll 1
        for (int kc = 0; kc < 8; kc++) {
            int it = mb * 8 + kc;
            if (it < 31) {
                int nx = it + 1, mb2 = nx >> 3, kc2 = nx & 7;
                copy_A_chunk(abuf[nx & 1], Ahb + (size_t)mb2 * 128 * DK,
                             Alb + (size_t)mb2 * 128 * DK, kc2 * 32);
                cp_commit();
                cp_wait<1>();
            } else {
                cp_wait<0>();
            }
            __syncthreads();
            compute_chunk_k2(abuf[it & 1], sb + K2_BH, kc * 64, lane, wm, wn, c);
            __syncthreads();
        }

        #pragma unroll
        for (int t = 0; t < 2; t++)
            #pragma unroll
            for (int n8 = 0; n8 < 4; n8++) {
                int n = nc + n8 * 8;
                float b0f = t2[n], b1f = t2[n + 1];
                #pragma unroll
                for (int h = 0; h < 2; h++) {
                    int m = mb * 128 + mr + t * 16 + h * 8;
                    float2 v;
                    v.x = c[t][n8][h * 2 + 0] + b0f;
                    v.y = c[t][n8][h * 2 + 1] + b1f;
                    *reinterpret_cast<float2*>(out + ((size_t)bl * 512 + m) * OD + n) = v;
                }
            }
    }
}

// ---------------- launch ----------------
extern "C" void kernel_launch(void* const* d_in, const int* in_sizes, int n_in,
                              void* d_out, int out_size) {
    const float* x1 = (const float*)d_in[0];   // (8,512,1,256)
    const float* x2 = (const float*)d_in[1];   // (8,1,512,256)
    const float* U  = (const float*)d_in[2];   // (64,257,257)
    float* out = (float*)d_out;                // (8,512,512,64)

    cudaFuncSetAttribute(t256_k, cudaFuncAttributeMaxDynamicSharedMemorySize, 83200);
    cudaFuncSetAttribute(k1_mm, cudaFuncAttributeMaxDynamicSharedMemorySize, (int)SMEMB);
    cudaFuncSetAttribute(k2_mm, cudaFuncAttributeMaxDynamicSharedMemorySize, (int)K2_SMEM);

    xsplit<<<8192, 256>>>(x1, x2);
    usplit<<<4096, 256>>>(U);
    t256_k<<<256, 256, 83200>>>(x1, U);
    k1_mm<<<dim3(32, 64, 4), 256, SMEMB>>>(U);
    k2_mm<<<4096, 256, K2_SMEM>>>(out);
}